// round 11
// baseline (speedup 1.0000x reference)
#include <cuda_runtime.h>
#include <cstdint>
#include <math.h>

#define FULL 0xffffffffu

static constexpr int B_   = 256;
static constexpr int D_   = 128;
static constexpr int DIN_ = 2048;
static constexpr int M_   = 4096;
static constexpr float TAU_INV = 1.0f / 0.07f;

// ---------------- device scratch ----------------
__device__ float g_raw[B_ * D_];        // un-normalized emb (+bias), 128 KB
__device__ float g_pssq[B_ * 32];       // per-d-slice partial sum-of-squares
__device__ float g_acc[2];              // [0]=sum data softplus, [1]=sum noise softplus

// ---------------- A: GEMM with W slice in SMEM -------------------------------
// grid 256 = 32 d-slices (4 cols) x 8 b-groups (32 rows). 256 threads = 8 warps,
// 3 blocks/SM target. Warp w owns 4 b-rows x 4 d-cols; lanes sweep K via float4.
// W slice (4 x 2048 fp32 = 32 KB) staged once in static smem.
__global__ void __launch_bounds__(256, 3)
kGemm(const float* __restrict__ outputs,
      const float* __restrict__ W,
      const float* __restrict__ bias) {
    __shared__ float4 sW4[4 * 512];       // 32 KB
    int ds  = blockIdx.x & 31;            // d-slice 0..31 (4 d each)
    int bgr = blockIdx.x >> 5;            // b-group 0..7 (32 b each)
    int tid = threadIdx.x, w = tid >> 5, lane = tid & 31;

    // stage W rows [ds*4, ds*4+4) -- coalesced, 8 float4 per thread
    {
        const float4* src = (const float4*)W + (size_t)(ds * 4) * (DIN_ / 4);
#pragma unroll
        for (int i = 0; i < 8; i++)
            sW4[i * 256 + tid] = src[i * 256 + tid];
    }
    __syncthreads();

    // mainloop: 4 b-rows per warp, 4 d each, K=2048 via 16 iters of 128
    int b0 = bgr * 32 + w * 4;
    const float4* o4 = (const float4*)outputs;

    float acc[4][4];
#pragma unroll
    for (int bi = 0; bi < 4; bi++)
#pragma unroll
        for (int dd = 0; dd < 4; dd++) acc[bi][dd] = 0.0f;

#pragma unroll 2
    for (int it = 0; it < 16; it++) {
        float4 ov[4];
#pragma unroll
        for (int bi = 0; bi < 4; bi++)
            ov[bi] = o4[(size_t)(b0 + bi) * (DIN_ / 4) + it * 32 + lane];
#pragma unroll
        for (int dd = 0; dd < 4; dd++) {
            float4 wv = sW4[dd * 512 + it * 32 + lane];
#pragma unroll
            for (int bi = 0; bi < 4; bi++) {
                float a = acc[bi][dd];
                a = fmaf(wv.x, ov[bi].x, a);
                a = fmaf(wv.y, ov[bi].y, a);
                a = fmaf(wv.z, ov[bi].z, a);
                a = fmaf(wv.w, ov[bi].w, a);
                acc[bi][dd] = a;
            }
        }
    }

    // reduce all 16 accs across lanes; lane bi*4+dd keeps its value
    float mine = 0.0f;
#pragma unroll
    for (int bi = 0; bi < 4; bi++)
#pragma unroll
        for (int dd = 0; dd < 4; dd++) {
            float r = acc[bi][dd];
#pragma unroll
            for (int o = 16; o; o >>= 1) r += __shfl_xor_sync(FULL, r, o);
            if (lane == bi * 4 + dd) mine = r;
        }

    if (lane < 16) {
        int dd_l = lane & 3, bi_l = lane >> 2;
        int d = ds * 4 + dd_l;
        int b = b0 + bi_l;
        mine += bias[d];
        g_raw[b * D_ + d] = mine;

        // partial sum-of-squares over this slice's 4 d (4-lane groups)
        float sq = mine * mine;
        sq += __shfl_xor_sync(0x0000ffffu, sq, 1);
        sq += __shfl_xor_sync(0x0000ffffu, sq, 2);
        if (dd_l == 0) g_pssq[b * 32 + ds] = sq;
    }

    if (blockIdx.x == 0 && tid == 0) { g_acc[0] = 0.0f; g_acc[1] = 0.0f; }
}

// ---------------- B: main gather + logsumexp + losses + entries --------------
// One block per batch row. 16 warps; warp w handles negs [w*256, w*256+256).
__global__ void __launch_bounds__(512, 2) kMain(
    const float* __restrict__ mbank,
    const int*   __restrict__ indices,
    const int*   __restrict__ ridx,
    float*       __restrict__ out) {
    int b = blockIdx.x;
    int tid = threadIdx.x, w = tid >> 5, lane = tid & 31;

    __shared__ float sneg[M_];
    __shared__ float sr[33];

    // normalize e on load: ssq = sum of 32 slice partials
    float ssq = g_pssq[b * 32 + lane];
#pragma unroll
    for (int o = 16; o; o >>= 1) ssq += __shfl_xor_sync(FULL, ssq, o);
    float inv = 1.0f / fmaxf(sqrtf(ssq), 1e-12f);

    float4 e = ((const float4*)g_raw)[b * 32 + lane];
    e.x *= inv; e.y *= inv; e.z *= inv; e.w *= inv;

    const float4* mb4 = (const float4*)mbank;
    const int* ri = ridx + (size_t)b * M_;

    // ---- gather + dot: 256 negs per warp ----
    int m0 = w * 256;
    for (int mb_ = m0; mb_ < m0 + 256; mb_ += 32) {
        int myIdx = ri[mb_ + lane];
#pragma unroll 8
        for (int j = 0; j < 32; j++) {
            int idx = __shfl_sync(FULL, myIdx, j);
            float4 v = mb4[(size_t)idx * 32 + lane];
            float d = v.x * e.x + v.y * e.y;
            d = fmaf(v.z, e.z, d);
            d = fmaf(v.w, e.w, d);
#pragma unroll
            for (int o = 16; o; o >>= 1) d += __shfl_xor_sync(FULL, d, o);
            if (lane == j) sneg[mb_ + j] = d * TAU_INV;
        }
    }
    __syncthreads();

    // ---- each thread owns 8 negs (stride 512, conflict-free) ----
    float vl[8];
    float mx = -3.0e38f;
#pragma unroll
    for (int i = 0; i < 8; i++) {
        vl[i] = sneg[tid + i * 512];
        mx = fmaxf(mx, vl[i]);
    }
#pragma unroll
    for (int o = 16; o; o >>= 1) mx = fmaxf(mx, __shfl_xor_sync(FULL, mx, o));
    if (lane == 0) sr[w] = mx;
    __syncthreads();
    if (w == 0) {
        float t2 = sr[lane & 15];
#pragma unroll
        for (int o = 8; o; o >>= 1) t2 = fmaxf(t2, __shfl_xor_sync(FULL, t2, o));
        if (lane == 0) sr[32] = t2;
    }
    __syncthreads();
    float Mx = sr[32];

    float se = 0.f;
#pragma unroll
    for (int i = 0; i < 8; i++) se += __expf(vl[i] - Mx);
#pragma unroll
    for (int o = 16; o; o >>= 1) se += __shfl_xor_sync(FULL, se, o);
    __syncthreads();
    if (lane == 0) sr[w] = se;
    __syncthreads();
    if (w == 0) {
        float t2 = (lane < 16) ? sr[lane] : 0.f;
#pragma unroll
        for (int o = 8; o; o >>= 1) t2 += __shfl_xor_sync(FULL, t2, o);
        if (lane == 0) sr[32] = Mx + __logf(t2);
    }
    __syncthreads();
    float logC = sr[32];

    // noise loss: sum softplus(neg - logC)
    float ns = 0.f;
#pragma unroll
    for (int i = 0; i < 8; i++) {
        float x = vl[i] - logC;
        ns += (x > 15.f) ? x : log1pf(__expf(x));
    }
#pragma unroll
    for (int o = 16; o; o >>= 1) ns += __shfl_xor_sync(FULL, ns, o);
    __syncthreads();
    if (lane == 0) sr[w] = ns;
    __syncthreads();
    if (w == 0) {
        float t2 = (lane < 16) ? sr[lane] : 0.f;
#pragma unroll
        for (int o = 8; o; o >>= 1) t2 += __shfl_xor_sync(FULL, t2, o);
        if (lane == 0) atomicAdd(&g_acc[1], t2);
    }

    // ---- warp 0: positive term + entries ----
    if (w == 0) {
        int pidx = indices[b];
        float4 p = mb4[(size_t)pidx * 32 + lane];
        float d = p.x * e.x + p.y * e.y;
        d = fmaf(p.z, e.z, d);
        d = fmaf(p.w, e.w, d);
#pragma unroll
        for (int o = 16; o; o >>= 1) d += __shfl_xor_sync(FULL, d, o);
        float pos = d * TAU_INV;

        float4 ent;
        ent.x = 0.5f * (p.x + e.x);
        ent.y = 0.5f * (p.y + e.y);
        ent.z = 0.5f * (p.z + e.z);
        ent.w = 0.5f * (p.w + e.w);
        float nsq = ent.x * ent.x + ent.y * ent.y + ent.z * ent.z + ent.w * ent.w;
#pragma unroll
        for (int o = 16; o; o >>= 1) nsq += __shfl_xor_sync(FULL, nsq, o);
        float inv2 = 1.0f / fmaxf(sqrtf(nsq), 1e-12f);
        ent.x *= inv2; ent.y *= inv2; ent.z *= inv2; ent.w *= inv2;

        int base = 1 + b * D_ + lane * 4;
        out[base + 0] = ent.x;
        out[base + 1] = ent.y;
        out[base + 2] = ent.z;
        out[base + 3] = ent.w;

        if (lane == 0) {
            float x = logC - pos;
            float dl = (x > 15.f) ? x : log1pf(__expf(x));
            atomicAdd(&g_acc[0], dl);
        }
    }
}

// ---------------- C: finalize scalars ----------------------------------------
__global__ void kFinal(float* __restrict__ out) {
    float dl = g_acc[0] * (1.0f / (float)B_);
    float nl = g_acc[1] * (1.0f / (float)B_);
    out[0] = dl + nl;
    out[1 + B_ * D_]     = dl;
    out[1 + B_ * D_ + 1] = nl;
}

// ---------------- launcher ----------------------------------------------------
extern "C" void kernel_launch(void* const* d_in, const int* in_sizes, int n_in,
                              void* d_out, int out_size) {
    const float* outputs = (const float*)d_in[0];
    const float* W       = (const float*)d_in[1];
    const float* bias    = (const float*)d_in[2];
    const float* mbank   = (const float*)d_in[3];
    const int*   indices = (const int*)d_in[4];
    const int*   ridx    = (const int*)d_in[5];
    float* out = (float*)d_out;

    kGemm<<<256, 256>>>(outputs, W, bias);
    kMain<<<256, 512>>>(mbank, indices, ridx, out);
    kFinal<<<1, 1>>>(out);
}

// round 12
// speedup vs baseline: 1.0046x; 1.0046x over previous
#include <cuda_runtime.h>
#include <cstdint>
#include <math.h>

#define FULL 0xffffffffu

static constexpr int B_   = 256;
static constexpr int D_   = 128;
static constexpr int DIN_ = 2048;
static constexpr int M_   = 4096;
static constexpr float TAU_INV = 1.0f / 0.07f;

// ---------------- device scratch ----------------
__device__ float g_raw[B_ * D_];        // un-normalized emb (+bias), 128 KB
__device__ float g_pssq[B_ * 32];       // per-d-slice partial sum-of-squares
__device__ float g_acc[2];              // [0]=sum data softplus, [1]=sum noise softplus

// ---------------- A: GEMM with W slice in SMEM (R9 config) -------------------
// grid 256 = 32 d-slices (4 cols) x 8 b-groups (32 rows). 256 threads = 8 warps,
// 2 blocks/SM. Warp w owns 4 b-rows x 4 d-cols; lanes sweep K via float4.
__global__ void __launch_bounds__(256, 2)
kGemm(const float* __restrict__ outputs,
      const float* __restrict__ W,
      const float* __restrict__ bias) {
    __shared__ float4 sW4[4 * 512];       // 32 KB
    int ds  = blockIdx.x & 31;            // d-slice 0..31 (4 d each)
    int bgr = blockIdx.x >> 5;            // b-group 0..7 (32 b each)
    int tid = threadIdx.x, w = tid >> 5, lane = tid & 31;

    // stage W rows [ds*4, ds*4+4) -- coalesced, 8 float4 per thread
    {
        const float4* src = (const float4*)W + (size_t)(ds * 4) * (DIN_ / 4);
#pragma unroll
        for (int i = 0; i < 8; i++)
            sW4[i * 256 + tid] = src[i * 256 + tid];
    }
    __syncthreads();

    // mainloop: 4 b-rows per warp, 4 d each, K=2048 via 16 iters of 128
    int b0 = bgr * 32 + w * 4;
    const float4* o4 = (const float4*)outputs;

    float acc[4][4];
#pragma unroll
    for (int bi = 0; bi < 4; bi++)
#pragma unroll
        for (int dd = 0; dd < 4; dd++) acc[bi][dd] = 0.0f;

#pragma unroll 4
    for (int it = 0; it < 16; it++) {
        float4 ov[4];
#pragma unroll
        for (int bi = 0; bi < 4; bi++)
            ov[bi] = o4[(size_t)(b0 + bi) * (DIN_ / 4) + it * 32 + lane];
#pragma unroll
        for (int dd = 0; dd < 4; dd++) {
            float4 wv = sW4[dd * 512 + it * 32 + lane];
#pragma unroll
            for (int bi = 0; bi < 4; bi++) {
                float a = acc[bi][dd];
                a = fmaf(wv.x, ov[bi].x, a);
                a = fmaf(wv.y, ov[bi].y, a);
                a = fmaf(wv.z, ov[bi].z, a);
                a = fmaf(wv.w, ov[bi].w, a);
                acc[bi][dd] = a;
            }
        }
    }

    // reduce all 16 accs across lanes; lane bi*4+dd keeps its value
    float mine = 0.0f;
#pragma unroll
    for (int bi = 0; bi < 4; bi++)
#pragma unroll
        for (int dd = 0; dd < 4; dd++) {
            float r = acc[bi][dd];
#pragma unroll
            for (int o = 16; o; o >>= 1) r += __shfl_xor_sync(FULL, r, o);
            if (lane == bi * 4 + dd) mine = r;
        }

    if (lane < 16) {
        int dd_l = lane & 3, bi_l = lane >> 2;
        int d = ds * 4 + dd_l;
        int b = b0 + bi_l;
        mine += bias[d];
        g_raw[b * D_ + d] = mine;

        // partial sum-of-squares over this slice's 4 d (4-lane groups)
        float sq = mine * mine;
        sq += __shfl_xor_sync(0x0000ffffu, sq, 1);
        sq += __shfl_xor_sync(0x0000ffffu, sq, 2);
        if (dd_l == 0) g_pssq[b * 32 + ds] = sq;
    }

    if (blockIdx.x == 0 && tid == 0) { g_acc[0] = 0.0f; g_acc[1] = 0.0f; }
}

// ---------------- B: main gather + logsumexp + losses + entries --------------
// One block per batch row. 16 warps; warp w handles negs [w*256, w*256+256).
// Index loads are software-pipelined one 32-row batch ahead.
__global__ void __launch_bounds__(512, 2) kMain(
    const float* __restrict__ mbank,
    const int*   __restrict__ indices,
    const int*   __restrict__ ridx,
    float*       __restrict__ out) {
    int b = blockIdx.x;
    int tid = threadIdx.x, w = tid >> 5, lane = tid & 31;

    __shared__ float sneg[M_];
    __shared__ float sr[33];

    // normalize e on load: ssq = sum of 32 slice partials
    float ssq = g_pssq[b * 32 + lane];
#pragma unroll
    for (int o = 16; o; o >>= 1) ssq += __shfl_xor_sync(FULL, ssq, o);
    float inv = 1.0f / fmaxf(sqrtf(ssq), 1e-12f);

    float4 e = ((const float4*)g_raw)[b * 32 + lane];
    e.x *= inv; e.y *= inv; e.z *= inv; e.w *= inv;

    const float4* mb4 = (const float4*)mbank;
    const int* ri = ridx + (size_t)b * M_;

    // ---- gather + dot: 256 negs per warp; idx loads pipelined 1 batch ahead --
    int m0 = w * 256;
    int myIdx = ri[m0 + lane];                    // prologue: batch 0 indices
    for (int mb_ = m0; mb_ < m0 + 256; mb_ += 32) {
        int curIdx = myIdx;
        if (mb_ + 32 < m0 + 256)
            myIdx = ri[mb_ + 32 + lane];          // prefetch next batch
#pragma unroll 8
        for (int j = 0; j < 32; j++) {
            int idx = __shfl_sync(FULL, curIdx, j);
            float4 v = mb4[(size_t)idx * 32 + lane];
            float d = v.x * e.x + v.y * e.y;
            d = fmaf(v.z, e.z, d);
            d = fmaf(v.w, e.w, d);
#pragma unroll
            for (int o = 16; o; o >>= 1) d += __shfl_xor_sync(FULL, d, o);
            if (lane == j) sneg[mb_ + j] = d * TAU_INV;
        }
    }
    __syncthreads();

    // ---- each thread owns 8 negs (stride 512, conflict-free) ----
    float vl[8];
    float mx = -3.0e38f;
#pragma unroll
    for (int i = 0; i < 8; i++) {
        vl[i] = sneg[tid + i * 512];
        mx = fmaxf(mx, vl[i]);
    }
#pragma unroll
    for (int o = 16; o; o >>= 1) mx = fmaxf(mx, __shfl_xor_sync(FULL, mx, o));
    if (lane == 0) sr[w] = mx;
    __syncthreads();
    if (w == 0) {
        float t2 = sr[lane & 15];
#pragma unroll
        for (int o = 8; o; o >>= 1) t2 = fmaxf(t2, __shfl_xor_sync(FULL, t2, o));
        if (lane == 0) sr[32] = t2;
    }
    __syncthreads();
    float Mx = sr[32];

    float se = 0.f;
#pragma unroll
    for (int i = 0; i < 8; i++) se += __expf(vl[i] - Mx);
#pragma unroll
    for (int o = 16; o; o >>= 1) se += __shfl_xor_sync(FULL, se, o);
    __syncthreads();
    if (lane == 0) sr[w] = se;
    __syncthreads();
    if (w == 0) {
        float t2 = (lane < 16) ? sr[lane] : 0.f;
#pragma unroll
        for (int o = 8; o; o >>= 1) t2 += __shfl_xor_sync(FULL, t2, o);
        if (lane == 0) sr[32] = Mx + __logf(t2);
    }
    __syncthreads();
    float logC = sr[32];

    // noise loss: sum softplus(neg - logC)
    float ns = 0.f;
#pragma unroll
    for (int i = 0; i < 8; i++) {
        float x = vl[i] - logC;
        ns += (x > 15.f) ? x : log1pf(__expf(x));
    }
#pragma unroll
    for (int o = 16; o; o >>= 1) ns += __shfl_xor_sync(FULL, ns, o);
    __syncthreads();
    if (lane == 0) sr[w] = ns;
    __syncthreads();
    if (w == 0) {
        float t2 = (lane < 16) ? sr[lane] : 0.f;
#pragma unroll
        for (int o = 8; o; o >>= 1) t2 += __shfl_xor_sync(FULL, t2, o);
        if (lane == 0) atomicAdd(&g_acc[1], t2);
    }

    // ---- warp 0: positive term + entries ----
    if (w == 0) {
        int pidx = indices[b];
        float4 p = mb4[(size_t)pidx * 32 + lane];
        float d = p.x * e.x + p.y * e.y;
        d = fmaf(p.z, e.z, d);
        d = fmaf(p.w, e.w, d);
#pragma unroll
        for (int o = 16; o; o >>= 1) d += __shfl_xor_sync(FULL, d, o);
        float pos = d * TAU_INV;

        float4 ent;
        ent.x = 0.5f * (p.x + e.x);
        ent.y = 0.5f * (p.y + e.y);
        ent.z = 0.5f * (p.z + e.z);
        ent.w = 0.5f * (p.w + e.w);
        float nsq = ent.x * ent.x + ent.y * ent.y + ent.z * ent.z + ent.w * ent.w;
#pragma unroll
        for (int o = 16; o; o >>= 1) nsq += __shfl_xor_sync(FULL, nsq, o);
        float inv2 = 1.0f / fmaxf(sqrtf(nsq), 1e-12f);
        ent.x *= inv2; ent.y *= inv2; ent.z *= inv2; ent.w *= inv2;

        int base = 1 + b * D_ + lane * 4;
        out[base + 0] = ent.x;
        out[base + 1] = ent.y;
        out[base + 2] = ent.z;
        out[base + 3] = ent.w;

        if (lane == 0) {
            float x = logC - pos;
            float dl = (x > 15.f) ? x : log1pf(__expf(x));
            atomicAdd(&g_acc[0], dl);
        }
    }
}

// ---------------- C: finalize scalars ----------------------------------------
__global__ void kFinal(float* __restrict__ out) {
    float dl = g_acc[0] * (1.0f / (float)B_);
    float nl = g_acc[1] * (1.0f / (float)B_);
    out[0] = dl + nl;
    out[1 + B_ * D_]     = dl;
    out[1 + B_ * D_ + 1] = nl;
}

// ---------------- launcher ----------------------------------------------------
extern "C" void kernel_launch(void* const* d_in, const int* in_sizes, int n_in,
                              void* d_out, int out_size) {
    const float* outputs = (const float*)d_in[0];
    const float* W       = (const float*)d_in[1];
    const float* bias    = (const float*)d_in[2];
    const float* mbank   = (const float*)d_in[3];
    const int*   indices = (const int*)d_in[4];
    const int*   ridx    = (const int*)d_in[5];
    float* out = (float*)d_out;

    kGemm<<<256, 256>>>(outputs, W, bias);
    kMain<<<256, 512>>>(mbank, indices, ridx, out);
    kFinal<<<1, 1>>>(out);
}